// round 16
// baseline (speedup 1.0000x reference)
#include <cuda_runtime.h>
#include <cuda_bf16.h>
#include <stdint.h>
#include <math.h>

#define BB 64
#define TT 512
#define DD 512
#define HH 512
#define G4H 2048  // 4*H

typedef unsigned long long ull;
typedef unsigned int u32;

// -------- device scratch (no cudaMalloc allowed) --------
__device__ float g_Zx[2][TT * BB][G4H];          // x-projection + bias
__device__ volatile unsigned g_phase[2];
__device__ volatile unsigned g_flag[2][64];      // per-CTA arrival flags
__device__ __nv_bfloat16 g_Ahi[TT * BB][DD];     // x reordered (m=t*B+b), bf16 hi
__device__ __nv_bfloat16 g_Alo[TT * BB][DD];     // bf16 lo
__device__ __nv_bfloat16 g_WT[2][2][G4H][DD];    // W[:512] transposed [dir][hi/lo][n][k]
__device__ __nv_bfloat16 g_WhT[2][2][G4H][DD];   // W[512:] transposed [dir][hi/lo][n][k]
// h state in MMA A-fragment layout: [dir][buf][split][k16 tile][mtile][lane][reg]
__device__ u32 g_hfrag[2][2][2][32 * 4 * 32 * 4];

// ---- helpers ----
#define CP_ASYNC16(smem_addr, gptr) \
    asm volatile("cp.async.cg.shared.global [%0], [%1], 16;" :: "r"(smem_addr), "l"(gptr))
#define CP_COMMIT()  asm volatile("cp.async.commit_group;")
#define CP_WAIT0()   asm volatile("cp.async.wait_group 0;" ::: "memory")
#define CP_WAIT1()   asm volatile("cp.async.wait_group 1;" ::: "memory")

// fast sigmoid/tanh: MUFU.EX2 + MUFU.RCP only (NaN-safe at +-inf of exp)
__device__ __forceinline__ float fsig(float x)  { return __fdividef(1.f, 1.f + __expf(-x)); }
__device__ __forceinline__ float ftanh(float x) { return __fdividef(2.f, 1.f + __expf(-2.f * x)) - 1.f; }

__device__ __forceinline__ void mma16816(float* c, const u32* a, u32 b0, u32 b1) {
    asm volatile(
        "mma.sync.aligned.m16n8k16.row.col.f32.bf16.bf16.f32 "
        "{%0,%1,%2,%3}, {%4,%5,%6,%7}, {%8,%9}, {%0,%1,%2,%3};"
        : "+f"(c[0]), "+f"(c[1]), "+f"(c[2]), "+f"(c[3])
        : "r"(a[0]), "r"(a[1]), "r"(a[2]), "r"(a[3]), "r"(b0), "r"(b1));
}

#define LDSM_X4(r0, r1, r2, r3, addr) \
    asm volatile("ldmatrix.sync.aligned.m8n8.x4.shared.b16 {%0,%1,%2,%3}, [%4];" \
                 : "=r"(r0), "=r"(r1), "=r"(r2), "=r"(r3) : "r"(addr))

__device__ __forceinline__ u32 smem_u32(const void* p) {
    u32 a;
    asm("{ .reg .u64 t; cvta.to.shared.u64 t, %1; cvt.u32.u64 %0, t; }" : "=r"(a) : "l"(p));
    return a;
}

// -------- prep: split x into bf16 hi/lo (m = t*B + b); init h/barrier state --------
__global__ void prep_ab(const float* __restrict__ x) {
    int idx = blockIdx.x * blockDim.x + threadIdx.x;
    int d = idx & 511;
    int m = idx >> 9;
    int t = m >> 6, b = m & 63;
    float v = x[((size_t)b * TT + t) * DD + d];
    __nv_bfloat16 hi = __float2bfloat16(v);
    float lo = v - __bfloat162float(hi);
    g_Ahi[m][d] = hi;
    g_Alo[m][d] = __float2bfloat16(lo);
    if (idx < 2 * 2 * 2 * 32 * 4 * 32 * 4)
        (&g_hfrag[0][0][0][0])[idx] = 0u;
    if (idx < 2 * 64) g_flag[idx >> 6][idx & 63] = 0;
    if (idx == 0) { g_phase[0] = 0; g_phase[1] = 0; }
}

// -------- prep: tiled transpose + bf16 hi/lo split of W (both halves) --------
__global__ void prep_w(const float* __restrict__ Wfw, const float* __restrict__ Wbw) {
    __shared__ float ts[32][33];
    int bid = blockIdx.x;
    int nt   = bid & 63;
    int kt   = (bid >> 6) & 15;
    int half = (bid >> 10) & 1;
    int dir  = bid >> 11;
    const float* Wm = dir ? Wbw : Wfw;

    int tx = threadIdx.x & 31;
    int ty = threadIdx.x >> 5;

#pragma unroll
    for (int i = ty; i < 32; i += 8)
        ts[i][tx] = Wm[(size_t)(half * 512 + kt * 32 + i) * G4H + nt * 32 + tx];
    __syncthreads();

    __nv_bfloat16* dhi = half ? &g_WhT[dir][0][0][0] : &g_WT[dir][0][0][0];
    __nv_bfloat16* dlo = half ? &g_WhT[dir][1][0][0] : &g_WT[dir][1][0][0];

#pragma unroll
    for (int i = ty; i < 32; i += 8) {
        float v = ts[tx][i];
        __nv_bfloat16 hi = __float2bfloat16(v);
        size_t o = (size_t)(nt * 32 + i) * DD + kt * 32 + tx;
        dhi[o] = hi;
        dlo[o] = __float2bfloat16(v - __bfloat162float(hi));
    }
}

// -------- mma.sync + ldmatrix x-projection GEMM (unchanged, verified) --------
#define PK      40
#define TILE_B  (128 * PK * 2)
#define PG_SMEM (8 * TILE_B)

__global__ void __launch_bounds__(256, 2)
pregemm_mma(const float* __restrict__ bfw, const float* __restrict__ bbw) {
    extern __shared__ char smc[];
    u32 smb = smem_u32(smc);
    int dir = blockIdx.z;
    int n0 = blockIdx.x * 128;
    int m0 = blockIdx.y * 128;
    const float* bias = dir ? bbw : bfw;

    int tid  = threadIdx.x;
    int warp = tid >> 5;
    int lane = tid & 31;
    int g  = lane >> 2;
    int tg = lane & 3;

    int wm = (warp & 3) * 32;
    int wn = (warp >> 2) * 64;

    int lrow  = tid >> 2;
    int lkcol = (tid & 3) * 8;
    const __nv_bfloat16* gsrc[4];
    gsrc[0] = &g_Ahi[m0][0];
    gsrc[1] = &g_Alo[m0][0];
    gsrc[2] = &g_WT[dir][0][n0][0];
    gsrc[3] = &g_WT[dir][1][n0][0];

    int rowA  = lane & 15;
    int koffA = (lane >> 4) * 8;
    int rowB  = (lane & 7) + ((lane >> 4) << 3);
    int koffB = ((lane >> 3) & 1) * 8;
    u32 aoff = (u32)(((wm + rowA) * PK + koffA) * 2);
    u32 boff = (u32)(((wn + rowB) * PK + koffB) * 2);

    float acc[2][8][4];
#pragma unroll
    for (int i = 0; i < 2; i++)
#pragma unroll
        for (int j = 0; j < 8; j++)
#pragma unroll
            for (int q = 0; q < 4; q++) acc[i][j][q] = 0.f;

    auto load_chunk = [&](int c, int buf) {
#pragma unroll
        for (int tile = 0; tile < 4; tile++) {
            u32 base = smb + (tile < 2 ? 0 : 4 * TILE_B) + (buf * 2 + (tile & 1)) * TILE_B;
#pragma unroll
            for (int it = 0; it < 2; it++) {
                int row = lrow + it * 64;
                const __nv_bfloat16* src = gsrc[tile] + (size_t)row * DD + c * 32 + lkcol;
                u32 dst = base + (u32)((row * PK + lkcol) * 2);
                CP_ASYNC16(dst, src);
            }
        }
        CP_COMMIT();
    };

    load_chunk(0, 0);

#pragma unroll 1
    for (int c = 0; c < 16; ++c) {
        int buf = c & 1;
        if (c < 15) { load_chunk(c + 1, buf ^ 1); CP_WAIT1(); }
        else        { CP_WAIT0(); }
        __syncthreads();

        u32 aBase0 = smb + (buf * 2 + 0) * TILE_B + aoff;
        u32 aBase1 = smb + (buf * 2 + 1) * TILE_B + aoff;
        u32 bBase0 = smb + 4 * TILE_B + (buf * 2 + 0) * TILE_B + boff;
        u32 bBase1 = smb + 4 * TILE_B + (buf * 2 + 1) * TILE_B + boff;

#pragma unroll
        for (int k16 = 0; k16 < 2; ++k16) {
            u32 kb = (u32)(k16 * 32);
            u32 ah[2][4], al[2][4];
#pragma unroll
            for (int mt = 0; mt < 2; mt++) {
                LDSM_X4(ah[mt][0], ah[mt][1], ah[mt][2], ah[mt][3],
                        aBase0 + kb + mt * (16 * PK * 2));
                LDSM_X4(al[mt][0], al[mt][1], al[mt][2], al[mt][3],
                        aBase1 + kb + mt * (16 * PK * 2));
            }
#pragma unroll
            for (int ng = 0; ng < 4; ng++) {
                u32 bh[4], bl[4];
                LDSM_X4(bh[0], bh[1], bh[2], bh[3], bBase0 + kb + ng * (16 * PK * 2));
                LDSM_X4(bl[0], bl[1], bl[2], bl[3], bBase1 + kb + ng * (16 * PK * 2));
#pragma unroll
                for (int mt = 0; mt < 2; mt++) {
                    mma16816(acc[mt][ng * 2],     ah[mt], bh[0], bh[1]);
                    mma16816(acc[mt][ng * 2 + 1], ah[mt], bh[2], bh[3]);
                    mma16816(acc[mt][ng * 2],     ah[mt], bl[0], bl[1]);
                    mma16816(acc[mt][ng * 2 + 1], ah[mt], bl[2], bl[3]);
                    mma16816(acc[mt][ng * 2],     al[mt], bh[0], bh[1]);
                    mma16816(acc[mt][ng * 2 + 1], al[mt], bh[2], bh[3]);
                }
            }
        }
        __syncthreads();
    }

#pragma unroll
    for (int nt = 0; nt < 8; nt++) {
        int col = n0 + wn + nt * 8 + 2 * tg;
        float b0 = bias[col], b1 = bias[col + 1];
#pragma unroll
        for (int mt = 0; mt < 2; mt++) {
            int row0 = m0 + wm + mt * 16 + g;
            float2 v0 = make_float2(acc[mt][nt][0] + b0, acc[mt][nt][1] + b1);
            float2 v1 = make_float2(acc[mt][nt][2] + b0, acc[mt][nt][3] + b1);
            *(float2*)&g_Zx[dir][row0][col]     = v0;
            *(float2*)&g_Zx[dir][row0 + 8][col] = v1;
        }
    }
}

// -------- flag-based per-direction grid barrier (no same-address atomics) --------
__device__ __forceinline__ void grid_barrier(int dir, int hb, unsigned target) {
    __syncthreads();
    if (threadIdx.x == 0) {
        __threadfence();                 // order hfrag stores before flag
        g_flag[dir][hb] = target;        // distinct address per CTA
    }
    if (hb == 0) {
        if (threadIdx.x < 64) {
            while (g_flag[dir][threadIdx.x] < target) { }
        }
        __syncthreads();                 // all 64 flags observed
        if (threadIdx.x == 0) {
            __threadfence();
            g_phase[dir] = target;
        }
    }
    if (threadIdx.x == 0) {
        while (g_phase[dir] < target) { }
        __threadfence();                 // L1 invalidate: fresh hfrag reads
    }
    __syncthreads();
}

// -------- persistent recurrent kernel: h in fragment layout, zero staging --------
#define PKH       520
#define B_SPLIT_B (32 * PKH * 2)            // 33280
#define Z_BYTES   (4 * 64 * 34 * 4)         // 34816
#define PERSIST_SMEM (Z_BYTES + 2 * B_SPLIT_B)   // 101376

__global__ void __launch_bounds__(512, 1)
lstm_persist(float* __restrict__ out) {
    extern __shared__ char smc[];
    u32 smb = smem_u32(smc);
    float* z_s = (float*)smc;                 // [4][64][34]

    int dir = blockIdx.y;
    int hb  = blockIdx.x;
    int h0  = hb * 8;

    int tid  = threadIdx.x;
    int warp = tid >> 5;
    int lane = tid & 31;
    int mt = warp & 3;          // m-tile: batch rows mt*16..
    int kg = warp >> 2;         // k-split: k in [kg*128, kg*128+128)

    // ---- load resident B slice (32 gathered n-rows x 512 k x 2 splits) ----
    for (int c = tid; c < 4096; c += 512) {
        int split = c >> 11;
        int r  = (c & 2047) >> 6;
        int ch = c & 63;
        int gate = r >> 3, hl = r & 7;
        const __nv_bfloat16* src = &g_WhT[dir][split][gate * 512 + h0 + hl][ch * 8];
        u32 dst = smb + Z_BYTES + split * B_SPLIT_B + (u32)(r * PKH * 2 + ch * 16);
        CP_ASYNC16(dst, src);
    }
    CP_COMMIT();

    // B fragment offsets (verified mapping)
    int rowB  = (lane & 7) + ((lane >> 4) << 3);
    int koffB = ((lane >> 3) & 1) * 8;
    u32 boff = (u32)((rowB * PKH + koffB) * 2);

    int pb = tid >> 3, phl = tid & 7;   // pointwise: 1 (b,h) per thread
    float c_reg = 0.f;

    // writer constants for fragment store
    int w_reg  = ((hb & 1) << 1) | ((pb >> 3) & 1);
    int w_lane = ((pb & 7) << 2) | (phl >> 1);
    int w_mt   = pb >> 4;
    size_t w_off = (((size_t)(hb >> 1) * 4 + w_mt) * 32 + w_lane) * 4 + w_reg;

    int zg = lane >> 2;
    int ztg = lane & 3;

    CP_WAIT0();
    __syncthreads();

#pragma unroll 1
    for (int t = 0; t < TT; ++t) {
        int tin = dir ? (TT - 1 - t) : t;
        int buf = t & 1;

        const u32* fr0 = &g_hfrag[dir][buf][0][0];
        const u32* fr1 = &g_hfrag[dir][buf][1][0];

        // ---- front-batch the first jj-block A fragments (hide L2 latency) ----
        uint4 fh[4], fl[4];
#pragma unroll
        for (int j = 0; j < 4; j++) {
            int tt = kg * 8 + j;
            size_t o = (((size_t)tt * 4 + mt) * 32 + lane) * 4;
            fh[j] = *(const uint4*)(fr0 + o);
            fl[j] = *(const uint4*)(fr1 + o);
        }

        // prefetch Zx for this step
        float rzx[4];
        {
            const float* zp = &g_Zx[dir][tin * BB + pb][h0 + phl];
#pragma unroll
            for (int g = 0; g < 4; g++) rzx[g] = zp[g * 512];
        }

        float acc[4][4];
#pragma unroll
        for (int i = 0; i < 4; i++)
#pragma unroll
            for (int q = 0; q < 4; q++) acc[i][q] = 0.f;

        u32 bBaseH = smb + Z_BYTES + boff;
        u32 bBaseL = smb + Z_BYTES + B_SPLIT_B + boff;

#pragma unroll
        for (int jj = 0; jj < 2; ++jj) {
#pragma unroll
            for (int j = 0; j < 4; j++) {
                u32 kb = (u32)((kg * 128 + (jj * 4 + j) * 16) * 2);
#pragma unroll
                for (int g2 = 0; g2 < 2; ++g2) {
                    u32 gofs = (u32)(g2 * 16 * PKH * 2);
                    u32 bh[4], bl[4];
                    LDSM_X4(bh[0], bh[1], bh[2], bh[3], bBaseH + kb + gofs);
                    LDSM_X4(bl[0], bl[1], bl[2], bl[3], bBaseL + kb + gofs);
                    const u32* ah = (const u32*)&fh[j];
                    const u32* al = (const u32*)&fl[j];
                    mma16816(acc[g2 * 2],     ah, bh[0], bh[1]);
                    mma16816(acc[g2 * 2 + 1], ah, bh[2], bh[3]);
                    mma16816(acc[g2 * 2],     ah, bl[0], bl[1]);
                    mma16816(acc[g2 * 2 + 1], ah, bl[2], bl[3]);
                    mma16816(acc[g2 * 2],     al, bh[0], bh[1]);
                    mma16816(acc[g2 * 2 + 1], al, bh[2], bh[3]);
                }
            }
            // load next jj-block fragments (overlaps current MMAs via scoreboard)
            if (jj == 0) {
#pragma unroll
                for (int j = 0; j < 4; j++) {
                    int tt = kg * 8 + 4 + j;
                    size_t o = (((size_t)tt * 4 + mt) * 32 + lane) * 4;
                    fh[j] = *(const uint4*)(fr0 + o);
                    fl[j] = *(const uint4*)(fr1 + o);
                }
            }
        }

        // ---- stash z partials (no pre-sync needed: readers passed grid barrier) ----
#pragma unroll
        for (int gate = 0; gate < 4; gate++) {
            int col = gate * 8 + 2 * ztg;
            *(float2*)&z_s[((kg * 64) + mt * 16 + zg) * 34 + col] =
                make_float2(acc[gate][0], acc[gate][1]);
            *(float2*)&z_s[((kg * 64) + mt * 16 + zg + 8) * 34 + col] =
                make_float2(acc[gate][2], acc[gate][3]);
        }
        __syncthreads();

        // ---- pointwise LSTM update + fragment-layout h store ----
        {
            int b = pb, hl = phl;
            float zi = rzx[0], zj = rzx[1], zf = rzx[2], zo = rzx[3];
#pragma unroll
            for (int g2 = 0; g2 < 4; g2++) {
                const float* zp = &z_s[(g2 * 64 + b) * 34];
                zi += zp[0 + hl];
                zj += zp[8 + hl];
                zf += zp[16 + hl];
                zo += zp[24 + hl];
            }

            float ig = fsig(zi);
            float jg = ftanh(zj);
            float fg = fsig(zf + 1.f);
            float og = fsig(zo);

            float cnew = fg * c_reg + ig * jg;
            float hnew = og * ftanh(cnew);
            c_reg = cnew;

            __nv_bfloat16 hhi = __float2bfloat16(hnew);
            __nv_bfloat16 hlo = __float2bfloat16(hnew - __bfloat162float(hhi));
            u32 vhi = (u32)__bfloat16_as_ushort(hhi);
            u32 vlo = (u32)__bfloat16_as_ushort(hlo);
            u32 phi = __shfl_down_sync(0xffffffffu, vhi, 1);
            u32 plo = __shfl_down_sync(0xffffffffu, vlo, 1);
            if ((hl & 1) == 0) {
                g_hfrag[dir][buf ^ 1][0][w_off] = vhi | (phi << 16);
                g_hfrag[dir][buf ^ 1][1][w_off] = vlo | (plo << 16);
            }
            out[((size_t)b * TT + tin) * (2 * HH) + dir * HH + h0 + hl] = hnew;
        }

        grid_barrier(dir, hb, (unsigned)(t + 1));
    }
}

extern "C" void kernel_launch(void* const* d_in, const int* in_sizes, int n_in,
                              void* d_out, int out_size) {
    const float* x   = (const float*)d_in[0];
    const float* Wfw = (const float*)d_in[1];
    const float* bfw = (const float*)d_in[2];
    const float* Wbw = (const float*)d_in[3];
    const float* bbw = (const float*)d_in[4];
    float* out = (float*)d_out;

    static int attr_done = 0;
    if (!attr_done) {
        cudaFuncSetAttribute(lstm_persist, cudaFuncAttributeMaxDynamicSharedMemorySize,
                             PERSIST_SMEM);
        cudaFuncSetAttribute(pregemm_mma, cudaFuncAttributeMaxDynamicSharedMemorySize,
                             PG_SMEM);
        attr_done = 1;
    }

    prep_ab<<<(TT * BB * DD) / 256, 256>>>(x);
    prep_w<<<4096, 256>>>(Wfw, Wbw);

    pregemm_mma<<<dim3(G4H / 128, (TT * BB) / 128, 2), 256, PG_SMEM>>>(bfw, bbw);

    lstm_persist<<<dim3(64, 2), 512, PERSIST_SMEM>>>(out);
}